// round 5
// baseline (speedup 1.0000x reference)
#include <cuda_runtime.h>
#include <cuda_bf16.h>
#include <cstdint>

// Problem constants (fixed by setup_inputs):
//   x: [65536, 256] f32,  A: [256, 1024] f32
//   out: [1024, 256, 256] f32  (G=1024 blocks of 256x256)
#define B_ROWS  65536
#define DIM     256            // K
#define HDIM    1024           // N total
#define MTILE   128            // rows per CTA
#define NCH     128            // N per chunk
#define NCHUNKS (HDIM / NCH)   // 8
#define NCTAS   (B_ROWS / MTILE) // 512

#define SKP     264                    // bf16 elems per padded SMEM row (528 B; odd 16B stride -> conflict-free)
#define SKPB    (SKP * 2)              // 528 bytes
#define XBYTES  (MTILE * SKPB)         // 67584
#define ABYTES  (NCH * SKPB)           // 67584
#define SMEM_BYTES (XBYTES + 2 * ABYTES) // 202752

// Device scratch: A^T in bf16, [N=1024][K=256] row-major
__device__ __nv_bfloat16 g_At[HDIM * DIM];

// ---------------- helpers ----------------
__device__ __forceinline__ uint32_t smem_u32(const void* p) {
    uint32_t a;
    asm("{ .reg .u64 t; cvta.to.shared.u64 t, %1; cvt.u32.u64 %0, t; }"
        : "=r"(a) : "l"(p));
    return a;
}

#define LDSM4(r0, r1, r2, r3, addr) \
    asm volatile("ldmatrix.sync.aligned.m8n8.x4.shared.b16 {%0,%1,%2,%3}, [%4];" \
                 : "=r"(r0), "=r"(r1), "=r"(r2), "=r"(r3) : "r"(addr))

#define MMA16816(c, a, b0, b1) \
    asm volatile("mma.sync.aligned.m16n8k16.row.col.f32.bf16.bf16.f32 " \
                 "{%0,%1,%2,%3}, {%4,%5,%6,%7}, {%8,%9}, {%0,%1,%2,%3};" \
                 : "+f"((c)[0]), "+f"((c)[1]), "+f"((c)[2]), "+f"((c)[3]) \
                 : "r"((a)[0]), "r"((a)[1]), "r"((a)[2]), "r"((a)[3]), "r"(b0), "r"(b1))

__device__ __forceinline__ float silu_f(float z) {
    float h = 0.5f * z;
    float t;
    asm("tanh.approx.f32 %0, %1;" : "=f"(t) : "f"(h));
    return fmaf(h, t, h);      // 0.5z + 0.5z*tanh(z/2) = silu(z)
}

// ---------------- A transpose+convert: A[k][n] f32 -> g_At[n][k] bf16 ----------------
__global__ void cvt_A_kernel(const float* __restrict__ A) {
    __shared__ float tile[32][33];
    int n0 = blockIdx.x * 32;
    int k0 = blockIdx.y * 32;
    int tx = threadIdx.x, ty = threadIdx.y;   // block (32, 8)
#pragma unroll
    for (int r = 0; r < 32; r += 8)
        tile[ty + r][tx] = A[(size_t)(k0 + ty + r) * HDIM + n0 + tx];
    __syncthreads();
#pragma unroll
    for (int r = 0; r < 32; r += 8)
        g_At[(size_t)(n0 + ty + r) * DIM + k0 + tx] = __float2bfloat16_rn(tile[tx][ty + r]);
}

// ---------------- fused GEMM(bf16 HMMA) + silu-rowsum + zero-fill + scatter ----------------
__global__ __launch_bounds__(256, 1)
void gemm_silu_kernel(const float* __restrict__ x, float* __restrict__ out) {
    extern __shared__ char smem_raw[];
    __shared__ float red[128];
    const uint32_t sx  = smem_u32(smem_raw);
    const uint32_t sa0 = sx + XBYTES;

    const int tid  = threadIdx.x;
    const int wid  = tid >> 5;        // 8 warps; warp w owns m-rows [16w, 16w+16)
    const int lane = tid & 31;
    const int ct   = blockIdx.x;
    const size_t b0 = (size_t)ct * MTILE;

    // ---- 1) zero-fill this CTA's 512KB output region (2 G-blocks); stores drain in background ----
    {
        float4 z4 = make_float4(0.f, 0.f, 0.f, 0.f);
        float4* zq = (float4*)(out + (size_t)ct * 131072);
#pragma unroll 4
        for (int j = 0; j < 128; j++) zq[tid + j * 256] = z4;
    }

    // ---- 2) prefetch At chunk 0 via cp.async ----
    {
#pragma unroll 4
        for (int j = 0; j < 16; j++) {
            int idx = tid + j * 256;          // 4096 x 16B
            int nl  = idx >> 5;               // 32 16B-chunks per row
            int kc  = idx & 31;
            uint32_t dst = sa0 + (uint32_t)nl * SKPB + (uint32_t)kc * 16;
            uint64_t src = __cvta_generic_to_global(g_At + (size_t)nl * DIM + kc * 8);
            asm volatile("cp.async.cg.shared.global [%0], [%1], 16;" :: "r"(dst), "l"(src));
        }
        asm volatile("cp.async.commit_group;" ::: "memory");
    }

    // ---- 3) load x tile [128,256] f32 -> bf16 SMEM (padded rows) ----
    {
        const float4* xg = (const float4*)(x + b0 * DIM);
#pragma unroll 4
        for (int j = 0; j < 32; j++) {
            int idx = tid + j * 256;          // 8192 float4
            int r = idx >> 6;                 // 64 float4 per row
            int c = idx & 63;
            float4 v = xg[idx];
            __nv_bfloat162 lo = __float22bfloat162_rn(make_float2(v.x, v.y));
            __nv_bfloat162 hi = __float22bfloat162_rn(make_float2(v.z, v.w));
            uint32_t addr = sx + (uint32_t)r * SKPB + (uint32_t)c * 8;
            asm volatile("st.shared.v2.b32 [%0], {%1,%2};"
                         :: "r"(addr), "r"(*(uint32_t*)&lo), "r"(*(uint32_t*)&hi) : "memory");
        }
    }
    __syncthreads();

    // ---- 4) load all 16 A-fragments (whole K) once; reused for every n-chunk ----
    uint32_t af[16][4];
    {
        int mat  = lane >> 3, row = lane & 7;
        int moff = ((mat & 1) << 3) + row;
        int koff = (mat >> 1) << 3;
        uint32_t base = sx + (uint32_t)(wid * 16 + moff) * SKPB + (uint32_t)koff * 2;
#pragma unroll
        for (int kk = 0; kk < 16; kk++) {
            uint32_t addr = base + (uint32_t)kk * 32;   // 16 bf16 = 32B per k-step
            LDSM4(af[kk][0], af[kk][1], af[kk][2], af[kk][3], addr);
        }
    }

    float rs0 = 0.f, rs1 = 0.f;   // row sums for m = 16w+gid and 16w+gid+8

    // ---- 5) n-chunk loop: cp.async double-buffered At, pipelined MMA + silu-rowsum ----
    for (int c = 0; c < NCHUNKS; c++) {
        if (c + 1 < NCHUNKS) {
            uint32_t sa_n = sa0 + (uint32_t)((c + 1) & 1) * ABYTES;
#pragma unroll 4
            for (int j = 0; j < 16; j++) {
                int idx = tid + j * 256;
                int nl  = idx >> 5;
                int kc  = idx & 31;
                uint32_t dst = sa_n + (uint32_t)nl * SKPB + (uint32_t)kc * 16;
                uint64_t src = __cvta_generic_to_global(
                    g_At + (size_t)((c + 1) * NCH + nl) * DIM + kc * 8);
                asm volatile("cp.async.cg.shared.global [%0], [%1], 16;" :: "r"(dst), "l"(src));
            }
            asm volatile("cp.async.commit_group;" ::: "memory");
            asm volatile("cp.async.wait_group 1;" ::: "memory");
        } else {
            asm volatile("cp.async.wait_group 0;" ::: "memory");
        }
        __syncthreads();

        const uint32_t sa = sa0 + (uint32_t)(c & 1) * ABYTES;
        const int brow = lane & 7, bmat = lane >> 3;
        const uint32_t bbase = sa + (uint32_t)brow * SKPB + (uint32_t)bmat * 16;

        // two n8 blocks in flight (nb, nb+1); two accumulator chains each (even/odd kb)
#pragma unroll
        for (int nb = 0; nb < 16; nb += 2) {
            const uint32_t ba0 = bbase + (uint32_t)nb * 8 * SKPB;
            const uint32_t ba1 = ba0 + 8u * SKPB;

            float cA[4] = {0.f, 0.f, 0.f, 0.f};   // nb,   even-kb chain
            float cB[4] = {0.f, 0.f, 0.f, 0.f};   // nb,   odd-kb chain
            float cC[4] = {0.f, 0.f, 0.f, 0.f};   // nb+1, even-kb chain
            float cD[4] = {0.f, 0.f, 0.f, 0.f};   // nb+1, odd-kb chain

            uint32_t bp[2][4], bq[2][4];          // double-buffered B frags (nb / nb+1)
            LDSM4(bp[0][0], bp[0][1], bp[0][2], bp[0][3], ba0);
            LDSM4(bq[0][0], bq[0][1], bq[0][2], bq[0][3], ba1);

#pragma unroll
            for (int kb = 0; kb < 8; kb++) {
                const int cur = kb & 1, nxt = cur ^ 1;
                if (kb < 7) {
                    LDSM4(bp[nxt][0], bp[nxt][1], bp[nxt][2], bp[nxt][3],
                          ba0 + (uint32_t)(kb + 1) * 64);
                    LDSM4(bq[nxt][0], bq[nxt][1], bq[nxt][2], bq[nxt][3],
                          ba1 + (uint32_t)(kb + 1) * 64);
                }
                MMA16816(cA, af[2 * kb],     bp[cur][0], bp[cur][1]);
                MMA16816(cC, af[2 * kb],     bq[cur][0], bq[cur][1]);
                MMA16816(cB, af[2 * kb + 1], bp[cur][2], bp[cur][3]);
                MMA16816(cD, af[2 * kb + 1], bq[cur][2], bq[cur][3]);
            }
            rs0 += silu_f(cA[0] + cB[0]) + silu_f(cA[1] + cB[1])
                 + silu_f(cC[0] + cD[0]) + silu_f(cC[1] + cD[1]);
            rs1 += silu_f(cA[2] + cB[2]) + silu_f(cA[3] + cB[3])
                 + silu_f(cC[2] + cD[2]) + silu_f(cC[3] + cD[3]);
        }
        __syncthreads();   // buffer (c&1) may be overwritten by next iteration's prefetch
    }

    // ---- 6) reduce across the 4 threads of each mma group, stage to shared ----
    rs0 += __shfl_xor_sync(0xFFFFFFFFu, rs0, 1);
    rs0 += __shfl_xor_sync(0xFFFFFFFFu, rs0, 2);
    rs1 += __shfl_xor_sync(0xFFFFFFFFu, rs1, 1);
    rs1 += __shfl_xor_sync(0xFFFFFFFFu, rs1, 2);
    if ((lane & 3) == 0) {
        int gid = lane >> 2;
        red[wid * 16 + gid]     = rs0;
        red[wid * 16 + gid + 8] = rs1;
    }
    __syncthreads();

    // ---- 7) scatter +/- s onto the block anti-diagonals (region already zeroed by this CTA) ----
    if (tid < 128) {
        float s = red[tid];
        size_t b = b0 + (size_t)tid;
        size_t g = b >> 6;                 // G block (64 rows per block)
        int i2 = (int)(b & 63) * 2;
        float* og = out + g * 65536;
        og[(size_t)i2 * 256 + 128 + i2]       =  s;   // top-right diag, even
        og[(size_t)(i2 + 1) * 256 + 129 + i2] =  s;   // top-right diag, odd
        og[(size_t)(128 + i2) * 256 + i2]     = -s;   // bottom-left diag, even
        og[(size_t)(129 + i2) * 256 + i2 + 1] = -s;   // bottom-left diag, odd
    }
}

// ---------------- launch ----------------
extern "C" void kernel_launch(void* const* d_in, const int* in_sizes, int n_in,
                              void* d_out, int out_size) {
    const float* x = (const float*)d_in[0];   // [65536, 256]
    const float* A = (const float*)d_in[1];   // [256, 1024]
    float* out = (float*)d_out;               // [1024, 256, 256]

    cudaFuncSetAttribute(gemm_silu_kernel,
                         cudaFuncAttributeMaxDynamicSharedMemorySize, SMEM_BYTES);

    cvt_A_kernel<<<dim3(32, 8), dim3(32, 8)>>>(A);
    gemm_silu_kernel<<<NCTAS, 256, SMEM_BYTES>>>(x, out);
}

// round 6
// speedup vs baseline: 1.1607x; 1.1607x over previous
#include <cuda_runtime.h>
#include <cuda_bf16.h>
#include <cstdint>

// Problem constants (fixed by setup_inputs):
//   x: [65536, 256] f32,  A: [256, 1024] f32
//   out: [1024, 256, 256] f32  (G=1024 blocks of 256x256)
#define B_ROWS  65536
#define DIM     256            // K
#define HDIM    1024           // N total
#define MTILE   128            // rows per CTA
#define NCH     64             // N per chunk
#define NCHUNKS (HDIM / NCH)   // 16
#define NCTAS   (B_ROWS / MTILE) // 512

#define SKP     264                    // bf16 elems per padded SMEM row (528 B; odd 16B stride -> conflict-free)
#define SKPB    (SKP * 2)              // 528 bytes
#define ABYTES  (NCH * SKPB)           // 33792
#define SMEM_BYTES (2 * ABYTES)        // 67584  -> 2 CTAs/SM

// Device scratch: A^T in bf16, [N=1024][K=256] row-major
__device__ __nv_bfloat16 g_At[HDIM * DIM];

// ---------------- helpers ----------------
__device__ __forceinline__ uint32_t smem_u32(const void* p) {
    uint32_t a;
    asm("{ .reg .u64 t; cvta.to.shared.u64 t, %1; cvt.u32.u64 %0, t; }"
        : "=r"(a) : "l"(p));
    return a;
}

#define LDSM4(r0, r1, r2, r3, addr) \
    asm volatile("ldmatrix.sync.aligned.m8n8.x4.shared.b16 {%0,%1,%2,%3}, [%4];" \
                 : "=r"(r0), "=r"(r1), "=r"(r2), "=r"(r3) : "r"(addr))

#define MMA16816(c, a, b0, b1) \
    asm volatile("mma.sync.aligned.m16n8k16.row.col.f32.bf16.bf16.f32 " \
                 "{%0,%1,%2,%3}, {%4,%5,%6,%7}, {%8,%9}, {%0,%1,%2,%3};" \
                 : "+f"((c)[0]), "+f"((c)[1]), "+f"((c)[2]), "+f"((c)[3]) \
                 : "r"((a)[0]), "r"((a)[1]), "r"((a)[2]), "r"((a)[3]), "r"(b0), "r"(b1))

__device__ __forceinline__ float silu_f(float z) {
    float h = 0.5f * z;
    float t;
    asm("tanh.approx.f32 %0, %1;" : "=f"(t) : "f"(h));
    return fmaf(h, t, h);      // 0.5z + 0.5z*tanh(z/2) = silu(z)
}

__device__ __forceinline__ uint32_t pack_bf16x2(float a, float b) {
    __nv_bfloat162 h = __float22bfloat162_rn(make_float2(a, b));
    return *(uint32_t*)&h;
}

// ---------------- A transpose+convert: A[k][n] f32 -> g_At[n][k] bf16 ----------------
__global__ void cvt_A_kernel(const float* __restrict__ A) {
    __shared__ float tile[32][33];
    int n0 = blockIdx.x * 32;
    int k0 = blockIdx.y * 32;
    int tx = threadIdx.x, ty = threadIdx.y;   // block (32, 8)
#pragma unroll
    for (int r = 0; r < 32; r += 8)
        tile[ty + r][tx] = A[(size_t)(k0 + ty + r) * HDIM + n0 + tx];
    __syncthreads();
#pragma unroll
    for (int r = 0; r < 32; r += 8)
        g_At[(size_t)(n0 + ty + r) * DIM + k0 + tx] = __float2bfloat16_rn(tile[tx][ty + r]);
}

// ---------------- fused GEMM(bf16 HMMA) + silu-rowsum + zero-fill + scatter ----------------
__global__ __launch_bounds__(256, 2)
void gemm_silu_kernel(const float* __restrict__ x, float* __restrict__ out) {
    extern __shared__ char smem_raw[];
    __shared__ float red[128];
    const uint32_t sa0 = smem_u32(smem_raw);

    const int tid  = threadIdx.x;
    const int wid  = tid >> 5;        // 8 warps; warp w owns m-rows [16w, 16w+16)
    const int lane = tid & 31;
    const int ct   = blockIdx.x;
    const size_t b0 = (size_t)ct * MTILE;

    // ---- 1) zero-fill this CTA's 512KB output region (2 G-blocks); stores drain in background ----
    {
        float4 z4 = make_float4(0.f, 0.f, 0.f, 0.f);
        float4* zq = (float4*)(out + (size_t)ct * 131072);
#pragma unroll 4
        for (int j = 0; j < 128; j++) zq[tid + j * 256] = z4;
    }

    // ---- 2) prefetch At chunk 0 via cp.async ----
    {
#pragma unroll
        for (int j = 0; j < 8; j++) {
            int idx = tid + j * 256;          // 2048 x 16B
            int nl  = idx >> 5;               // 32 16B-chunks per row
            int kc  = idx & 31;
            uint32_t dst = sa0 + (uint32_t)nl * SKPB + (uint32_t)kc * 16;
            uint64_t src = __cvta_generic_to_global(g_At + (size_t)nl * DIM + kc * 8);
            asm volatile("cp.async.cg.shared.global [%0], [%1], 16;" :: "r"(dst), "l"(src));
        }
        asm volatile("cp.async.commit_group;" ::: "memory");
    }

    // ---- 3) load A-fragments for all K directly from global x (f32 -> bf16 packs) ----
    // m16n8k16 A frag, thread t: g = t>>2 (row in 8x8), q = t&3 (k-pair)
    // a0 = x[m_lo][2q,2q+1], a1 = x[m_hi][2q..], a2 = x[m_lo][2q+8..], a3 = x[m_hi][2q+8..]
    uint32_t af[16][4];
    {
        int g = lane >> 2, q = lane & 3;
        const float* xr0 = x + (b0 + (size_t)(wid * 16 + g)) * DIM;   // m_lo row
        const float* xr1 = xr0 + 8 * DIM;                             // m_hi row
#pragma unroll
        for (int kk = 0; kk < 16; kk++) {
            int k0 = kk * 16 + 2 * q;
            float2 v00 = *(const float2*)(xr0 + k0);
            float2 v10 = *(const float2*)(xr1 + k0);
            float2 v01 = *(const float2*)(xr0 + k0 + 8);
            float2 v11 = *(const float2*)(xr1 + k0 + 8);
            af[kk][0] = pack_bf16x2(v00.x, v00.y);
            af[kk][1] = pack_bf16x2(v10.x, v10.y);
            af[kk][2] = pack_bf16x2(v01.x, v01.y);
            af[kk][3] = pack_bf16x2(v11.x, v11.y);
        }
    }

    float rs0 = 0.f, rs1 = 0.f;   // row sums for m = 16w+g and 16w+g+8

    // ---- 4) n-chunk loop: cp.async double-buffered At, MMA + silu-rowsum ----
    const int brow = lane & 7, bmat = lane >> 3;
    for (int c = 0; c < NCHUNKS; c++) {
        if (c + 1 < NCHUNKS) {
            uint32_t sa_n = sa0 + (uint32_t)((c + 1) & 1) * ABYTES;
#pragma unroll
            for (int j = 0; j < 8; j++) {
                int idx = tid + j * 256;
                int nl  = idx >> 5;
                int kc  = idx & 31;
                uint32_t dst = sa_n + (uint32_t)nl * SKPB + (uint32_t)kc * 16;
                uint64_t src = __cvta_generic_to_global(
                    g_At + (size_t)((c + 1) * NCH + nl) * DIM + kc * 8);
                asm volatile("cp.async.cg.shared.global [%0], [%1], 16;" :: "r"(dst), "l"(src));
            }
            asm volatile("cp.async.commit_group;" ::: "memory");
            asm volatile("cp.async.wait_group 1;" ::: "memory");
        } else {
            asm volatile("cp.async.wait_group 0;" ::: "memory");
        }
        __syncthreads();

        const uint32_t sa = sa0 + (uint32_t)(c & 1) * ABYTES;
        const uint32_t bbase = sa + (uint32_t)brow * SKPB + (uint32_t)bmat * 16;

#pragma unroll
        for (int nb = 0; nb < 8; nb++) {
            const uint32_t ba = bbase + (uint32_t)nb * 8 * SKPB;
            float cA[4] = {0.f, 0.f, 0.f, 0.f};   // even-kb chain
            float cB[4] = {0.f, 0.f, 0.f, 0.f};   // odd-kb chain
            uint32_t bp[2][4];                    // double-buffered B frags
            LDSM4(bp[0][0], bp[0][1], bp[0][2], bp[0][3], ba);
#pragma unroll
            for (int kb = 0; kb < 8; kb++) {
                const int cur = kb & 1;
                if (kb < 7) {
                    LDSM4(bp[cur ^ 1][0], bp[cur ^ 1][1], bp[cur ^ 1][2], bp[cur ^ 1][3],
                          ba + (uint32_t)(kb + 1) * 64);
                }
                MMA16816(cA, af[2 * kb],     bp[cur][0], bp[cur][1]);
                MMA16816(cB, af[2 * kb + 1], bp[cur][2], bp[cur][3]);
            }
            rs0 += silu_f(cA[0] + cB[0]) + silu_f(cA[1] + cB[1]);
            rs1 += silu_f(cA[2] + cB[2]) + silu_f(cA[3] + cB[3]);
        }
        __syncthreads();   // buffer (c&1) may be overwritten by next iteration's prefetch
    }

    // ---- 5) reduce across the 4 threads of each mma group, stage to shared ----
    rs0 += __shfl_xor_sync(0xFFFFFFFFu, rs0, 1);
    rs0 += __shfl_xor_sync(0xFFFFFFFFu, rs0, 2);
    rs1 += __shfl_xor_sync(0xFFFFFFFFu, rs1, 1);
    rs1 += __shfl_xor_sync(0xFFFFFFFFu, rs1, 2);
    if ((lane & 3) == 0) {
        int gid = lane >> 2;
        red[wid * 16 + gid]     = rs0;
        red[wid * 16 + gid + 8] = rs1;
    }
    __syncthreads();

    // ---- 6) scatter +/- s onto the block anti-diagonals (region already zeroed by this CTA) ----
    if (tid < 128) {
        float s = red[tid];
        size_t b = b0 + (size_t)tid;
        size_t g = b >> 6;                 // G block (64 rows per block)
        int i2 = (int)(b & 63) * 2;
        float* og = out + g * 65536;
        og[(size_t)i2 * 256 + 128 + i2]       =  s;   // top-right diag, even
        og[(size_t)(i2 + 1) * 256 + 129 + i2] =  s;   // top-right diag, odd
        og[(size_t)(128 + i2) * 256 + i2]     = -s;   // bottom-left diag, even
        og[(size_t)(129 + i2) * 256 + i2 + 1] = -s;   // bottom-left diag, odd
    }
}

// ---------------- launch ----------------
extern "C" void kernel_launch(void* const* d_in, const int* in_sizes, int n_in,
                              void* d_out, int out_size) {
    const float* x = (const float*)d_in[0];   // [65536, 256]
    const float* A = (const float*)d_in[1];   // [256, 1024]
    float* out = (float*)d_out;               // [1024, 256, 256]

    cudaFuncSetAttribute(gemm_silu_kernel,
                         cudaFuncAttributeMaxDynamicSharedMemorySize, SMEM_BYTES);

    cvt_A_kernel<<<dim3(32, 8), dim3(32, 8)>>>(A);
    gemm_silu_kernel<<<NCTAS, 256, SMEM_BYTES>>>(x, out);
}